// round 7
// baseline (speedup 1.0000x reference)
#include <cuda_runtime.h>
#include <stdint.h>

// XNOR binarized linear: warp-broadcast popc, 4-way column split, 64-reg cap.
// y[n,o] = (256 - 2*popc(xbits[n] ^ wbits[o])) * scale[o]
//
// Block = 256 thr / 8 warps: (warp&1)=row subset (32 rows), (warp>>1)=column
// quarter (64 cols). Lane L owns cols q*64+2L, 2L+1 -> one STG.64 per row.
// Every warp ballots its rows itself (FSETP/VOTE pipes are idle; alu pipe
// unaffected by the split). No smem, no barriers.

constexpr int NROWS = 262144;
constexpr int DIM   = 256;
constexpr int WPR   = 8;

constexpr int CHUNK_ROWS = 64;
constexpr int NCHUNK     = NROWS / CHUNK_ROWS;   // 4096
constexpr int GRID       = 592;                  // 148 SMs x 4 blocks

__device__ uint32_t g_wbits[DIM * WPR];

// ---------------------------------------------------------------------------
// Pre-kernel: pack weight sign bits (one warp per output row).
// Word (h*4+c), bit L  <->  element h*128 + 4L + c. Matches x packing below.
// ---------------------------------------------------------------------------
__global__ void pack_w_kernel(const float* __restrict__ w) {
    int warp = (blockIdx.x * blockDim.x + threadIdx.x) >> 5;
    int lane = threadIdx.x & 31;
    if (warp >= DIM) return;
    const float4* row = reinterpret_cast<const float4*>(w) + (size_t)warp * (DIM / 4);
#pragma unroll
    for (int h = 0; h < 2; ++h) {
        float4 v = row[h * 32 + lane];
        uint32_t m0 = __ballot_sync(0xFFFFFFFFu, v.x < 0.0f);
        uint32_t m1 = __ballot_sync(0xFFFFFFFFu, v.y < 0.0f);
        uint32_t m2 = __ballot_sync(0xFFFFFFFFu, v.z < 0.0f);
        uint32_t m3 = __ballot_sync(0xFFFFFFFFu, v.w < 0.0f);
        if (lane == 0) {
            *reinterpret_cast<uint4*>(&g_wbits[warp * WPR + h * 4]) =
                make_uint4(m0, m1, m2, m3);
        }
    }
}

// ---------------------------------------------------------------------------
// Main kernel.
// ---------------------------------------------------------------------------
__global__ void __launch_bounds__(256, 4)
xnor_q4_kernel(const float* __restrict__ x,
               const float* __restrict__ scale,
               float* __restrict__ out) {
    const int warp  = threadIdx.x >> 5;
    const int lane  = threadIdx.x & 31;
    const int rsub  = warp & 1;      // row subset (32 rows)
    const int q     = warp >> 1;     // column quarter (64 cols)

    // Two adjacent output columns per lane: o0 = q*64 + 2*lane, o1 = o0+1.
    const int o0 = q * 64 + 2 * lane;
    uint4 wlo0 = *reinterpret_cast<const uint4*>(&g_wbits[o0 * WPR]);
    uint4 whi0 = *reinterpret_cast<const uint4*>(&g_wbits[o0 * WPR + 4]);
    uint4 wlo1 = *reinterpret_cast<const uint4*>(&g_wbits[(o0 + 1) * WPR]);
    uint4 whi1 = *reinterpret_cast<const uint4*>(&g_wbits[(o0 + 1) * WPR + 4]);
    const float2 S = *reinterpret_cast<const float2*>(scale + o0);

    constexpr uint32_t MAGIC256 = 0x4B400000u + 256u;   // 2^23*1.5 + 256

    const float4* x4 = reinterpret_cast<const float4*>(x);

    for (int ch = blockIdx.x; ch < NCHUNK; ch += gridDim.x) {
        const int row0 = ch * CHUNK_ROWS + rsub * 32;
        const float4* rp = x4 + (size_t)row0 * (DIM / 4);
        float* obase = out + (size_t)row0 * DIM + o0;

        // depth-2 prefetch: rows r (c), r+1 (d) in flight
        float4 c0 = rp[lane];       float4 c1 = rp[32 + lane];
        float4 d0 = rp[64 + lane];  float4 d1 = rp[96 + lane];

#pragma unroll 2
        for (int r = 0; r < 32; ++r) {
            // issue row r+2 (clamped)
            const int rn = (r + 2 < 32) ? r + 2 : 31;
            float4 e0 = rp[rn * 64 + lane];
            float4 e1 = rp[rn * 64 + 32 + lane];

            // ballot-transpose row r's sign bits (broadcast to all lanes)
            uint32_t b0 = __ballot_sync(0xFFFFFFFFu, c0.x < 0.0f);
            uint32_t b1 = __ballot_sync(0xFFFFFFFFu, c0.y < 0.0f);
            uint32_t b2 = __ballot_sync(0xFFFFFFFFu, c0.z < 0.0f);
            uint32_t b3 = __ballot_sync(0xFFFFFFFFu, c0.w < 0.0f);
            uint32_t b4 = __ballot_sync(0xFFFFFFFFu, c1.x < 0.0f);
            uint32_t b5 = __ballot_sync(0xFFFFFFFFu, c1.y < 0.0f);
            uint32_t b6 = __ballot_sync(0xFFFFFFFFu, c1.z < 0.0f);
            uint32_t b7 = __ballot_sync(0xFFFFFFFFu, c1.w < 0.0f);

            // two independent popc chains (adjacent output columns)
            int p0 = __popc(b0 ^ wlo0.x) + __popc(b1 ^ wlo0.y) +
                     __popc(b2 ^ wlo0.z) + __popc(b3 ^ wlo0.w) +
                     __popc(b4 ^ whi0.x) + __popc(b5 ^ whi0.y) +
                     __popc(b6 ^ whi0.z) + __popc(b7 ^ whi0.w);
            int p1 = __popc(b0 ^ wlo1.x) + __popc(b1 ^ wlo1.y) +
                     __popc(b2 ^ wlo1.z) + __popc(b3 ^ wlo1.w) +
                     __popc(b4 ^ whi1.x) + __popc(b5 ^ whi1.y) +
                     __popc(b6 ^ whi1.z) + __popc(b7 ^ whi1.w);

            // exact epilogue: fd = float(256-2p) exactly, then single rounding
            uint32_t t0 = MAGIC256 - 2u * (uint32_t)p0;
            uint32_t t1 = MAGIC256 - 2u * (uint32_t)p1;
            float2 y;
            y.x = (__uint_as_float(t0) - 12582912.0f) * S.x;
            y.y = (__uint_as_float(t1) - 12582912.0f) * S.y;
            *reinterpret_cast<float2*>(obase + (size_t)r * DIM) = y;  // STG.64

            c0 = d0; c1 = d1; d0 = e0; d1 = e1;
        }
    }
}

// ---------------------------------------------------------------------------
// kernel_launch: d_in[0]=x [N,256] f32, d_in[1]=weight [256,256] f32,
//                d_in[2]=scale [1,256] f32; d_out = y [N,256] f32.
// ---------------------------------------------------------------------------
extern "C" void kernel_launch(void* const* d_in, const int* in_sizes, int n_in,
                              void* d_out, int out_size) {
    const float* x      = (const float*)d_in[0];
    const float* weight = (const float*)d_in[1];
    const float* scale  = (const float*)d_in[2];
    float* out          = (float*)d_out;
    (void)in_sizes; (void)n_in; (void)out_size;

    pack_w_kernel<<<32, 256>>>(weight);
    xnor_q4_kernel<<<GRID, 256>>>(x, scale, out);
}

// round 8
// speedup vs baseline: 1.0584x; 1.0584x over previous
#include <cuda_runtime.h>
#include <stdint.h>

// XNOR binarized linear: lane-owns-row, weights broadcast from smem.
// y[n,o] = (256 - 2*popc(xbits[n] ^ wbits[o])) * scale[o]
//
// Block = 256 thr / 8 warps; each warp owns 32 rows (lane L holds row L's
// 256 packed sign bits in 8 registers, built via ballots). Phase 2 iterates
// all 256 outputs: weight words come from smem via broadcast LDS (all lanes
// same address), results staged in smem (stride-17, conflict-free) and
// written out transposed as coalesced STG.128.

constexpr int NROWS = 262144;
constexpr int DIM   = 256;
constexpr int WPR   = 8;

constexpr int WARPS      = 8;
constexpr int BLOCK_ROWS = 32 * WARPS;            // 256 rows per block
constexpr int NCHUNK     = NROWS / BLOCK_ROWS;    // 1024 blocks

__device__ uint32_t g_wbits[DIM * WPR];

// ---------------------------------------------------------------------------
// Pre-kernel: pack weight sign bits (one warp per output row).
// Word (h*4+c), bit L  <->  element h*128 + 4L + c. Matches x packing below.
// ---------------------------------------------------------------------------
__global__ void pack_w_kernel(const float* __restrict__ w) {
    int warp = (blockIdx.x * blockDim.x + threadIdx.x) >> 5;
    int lane = threadIdx.x & 31;
    if (warp >= DIM) return;
    const float4* row = reinterpret_cast<const float4*>(w) + (size_t)warp * (DIM / 4);
#pragma unroll
    for (int h = 0; h < 2; ++h) {
        float4 v = row[h * 32 + lane];
        uint32_t m0 = __ballot_sync(0xFFFFFFFFu, v.x < 0.0f);
        uint32_t m1 = __ballot_sync(0xFFFFFFFFu, v.y < 0.0f);
        uint32_t m2 = __ballot_sync(0xFFFFFFFFu, v.z < 0.0f);
        uint32_t m3 = __ballot_sync(0xFFFFFFFFu, v.w < 0.0f);
        if (lane == 0) {
            *reinterpret_cast<uint4*>(&g_wbits[warp * WPR + h * 4]) =
                make_uint4(m0, m1, m2, m3);
        }
    }
}

// ---------------------------------------------------------------------------
// Main kernel.
// ---------------------------------------------------------------------------
__global__ void __launch_bounds__(256, 5)
xnor_rowlane_kernel(const float* __restrict__ x,
                    const float* __restrict__ scale,
                    float* __restrict__ out) {
    __shared__ uint32_t sw[DIM * WPR];               // weights, 8 KB
    __shared__ float    ss[DIM];                     // scales, 1 KB
    __shared__ uint32_t stage[WARPS][32][17];        // transpose stage, 17.4 KB

    const int tid  = threadIdx.x;
    const int warp = tid >> 5;
    const int lane = tid & 31;

    // ---- init weights + scales into smem (once per block) ----
    {
        const uint4* gw = reinterpret_cast<const uint4*>(g_wbits);
        uint4* swv = reinterpret_cast<uint4*>(sw);
        swv[tid]       = gw[tid];
        swv[tid + 256] = gw[tid + 256];
        ss[tid] = scale[tid];
    }

    // ---- phase 1: ballot-pack this warp's 32 rows; lane r keeps row r ----
    uint32_t mb0, mb1, mb2, mb3, mb4, mb5, mb6, mb7;
    const int rowBase = blockIdx.x * BLOCK_ROWS + warp * 32;
    {
        const float4* rp = reinterpret_cast<const float4*>(x) +
                           (size_t)rowBase * (DIM / 4);
        float4 c0 = rp[lane];       float4 c1 = rp[32 + lane];
        float4 d0 = rp[64 + lane];  float4 d1 = rp[96 + lane];
#pragma unroll
        for (int r = 0; r < 32; ++r) {
            const int rn = (r + 2 < 32) ? r + 2 : 31;
            float4 e0 = rp[rn * 64 + lane];
            float4 e1 = rp[rn * 64 + 32 + lane];

            uint32_t b0 = __ballot_sync(0xFFFFFFFFu, c0.x < 0.0f);
            uint32_t b1 = __ballot_sync(0xFFFFFFFFu, c0.y < 0.0f);
            uint32_t b2 = __ballot_sync(0xFFFFFFFFu, c0.z < 0.0f);
            uint32_t b3 = __ballot_sync(0xFFFFFFFFu, c0.w < 0.0f);
            uint32_t b4 = __ballot_sync(0xFFFFFFFFu, c1.x < 0.0f);
            uint32_t b5 = __ballot_sync(0xFFFFFFFFu, c1.y < 0.0f);
            uint32_t b6 = __ballot_sync(0xFFFFFFFFu, c1.z < 0.0f);
            uint32_t b7 = __ballot_sync(0xFFFFFFFFu, c1.w < 0.0f);
            if (lane == r) {
                mb0 = b0; mb1 = b1; mb2 = b2; mb3 = b3;
                mb4 = b4; mb5 = b5; mb6 = b6; mb7 = b7;
            }
            c0 = d0; c1 = d1; d0 = e0; d1 = e1;
        }
    }
    __syncthreads();   // weights/scales visible

    // ---- phase 2: all 256 outputs; weights broadcast from smem ----
    constexpr uint32_t MAGIC256 = 0x4B400000u + 256u;   // 2^23*1.5 + 256

#pragma unroll 1
    for (int och = 0; och < 16; ++och) {
#pragma unroll
        for (int oo = 0; oo < 16; ++oo) {
            const int o = och * 16 + oo;
            const uint4 w0 = *reinterpret_cast<const uint4*>(&sw[o * WPR]);
            const uint4 w1 = *reinterpret_cast<const uint4*>(&sw[o * WPR + 4]);
            int p = __popc(mb0 ^ w0.x) + __popc(mb1 ^ w0.y) +
                    __popc(mb2 ^ w0.z) + __popc(mb3 ^ w0.w) +
                    __popc(mb4 ^ w1.x) + __popc(mb5 ^ w1.y) +
                    __popc(mb6 ^ w1.z) + __popc(mb7 ^ w1.w);
            uint32_t t = MAGIC256 - 2u * (uint32_t)p;        // IMAD
            float y = (__uint_as_float(t) - 12582912.0f) * ss[o];
            stage[warp][lane][oo] = __float_as_uint(y);      // conflict-free
        }
        __syncwarp();

        // transpose-out: 4 phases, each 8 rows x 16B/row-chunk, STG.128
#pragma unroll
        for (int ph = 0; ph < 4; ++ph) {
            const int r = ph * 8 + (lane >> 2);
            const int c = (lane & 3) * 4;
            uint4 v;
            v.x = stage[warp][r][c];
            v.y = stage[warp][r][c + 1];
            v.z = stage[warp][r][c + 2];
            v.w = stage[warp][r][c + 3];
            *reinterpret_cast<uint4*>(out + (size_t)(rowBase + r) * DIM +
                                      och * 16 + c) = v;
        }
        __syncwarp();
    }
}

// ---------------------------------------------------------------------------
// kernel_launch: d_in[0]=x [N,256] f32, d_in[1]=weight [256,256] f32,
//                d_in[2]=scale [1,256] f32; d_out = y [N,256] f32.
// ---------------------------------------------------------------------------
extern "C" void kernel_launch(void* const* d_in, const int* in_sizes, int n_in,
                              void* d_out, int out_size) {
    const float* x      = (const float*)d_in[0];
    const float* weight = (const float*)d_in[1];
    const float* scale  = (const float*)d_in[2];
    float* out          = (float*)d_out;
    (void)in_sizes; (void)n_in; (void)out_size;

    pack_w_kernel<<<32, 256>>>(weight);
    xnor_rowlane_kernel<<<NCHUNK, 256>>>(x, scale, out);
}